// round 5
// baseline (speedup 1.0000x reference)
#include <cuda_runtime.h>
#include <math.h>

// Shapes
#define DIMC 192
#define HW   1024
#define BATCH 32
#define GRAMD 18528   // 192*193/2
#define N1 9264
#define N2 4632
#define N3 64

// Scratch (device globals: no allocation allowed in kernel_launch)
__device__ float g_buf[BATCH * GRAMD];
__device__ float h1_buf[BATCH * N1];
__device__ float h2_buf[BATCH * N2];
__device__ float h3_buf[BATCH * N3];

// Packed f32x2 FMA: d = a*b + d  (two independent fp32 lanes in one issue slot)
__device__ __forceinline__ void ffma2(unsigned long long& d,
                                      unsigned long long a,
                                      unsigned long long b)
{
    asm("fma.rn.f32x2 %0, %1, %2, %0;" : "+l"(d) : "l"(a), "l"(b));
}

__device__ __forceinline__ float fold_f32x2(unsigned long long v)
{
    float2 f = *reinterpret_cast<float2*>(&v);
    return f.x + f.y;
}

// ---------------------------------------------------------------------------
// Kernel 1: per-sample Gram upper-triangle features (f32x2 inner loop).
// grid = (6 tile-pairs, 32 batch), block = 256 threads (16x16), 4x4 micro-tile.
// Row padding = 18 floats: keeps float2 (8B) alignment and conflict-free banks.
// ---------------------------------------------------------------------------
__global__ void gram_kernel(const float* __restrict__ x, float* __restrict__ g)
{
    __shared__ float As[64][18];
    __shared__ float Bs[64][18];

    const int TI[6] = {0, 0, 0, 1, 1, 2};
    const int TJ[6] = {0, 1, 2, 1, 2, 2};

    int pair = blockIdx.x;
    int b    = blockIdx.y;
    int ti = TI[pair], tj = TJ[pair];

    const float* feat = x + (size_t)b * DIMC * HW;

    int t  = threadIdx.x;
    int ty = t >> 4;      // 0..15
    int tx = t & 15;      // 0..15

    unsigned long long acc[4][4];
    #pragma unroll
    for (int i = 0; i < 4; i++)
        #pragma unroll
        for (int j = 0; j < 4; j++) acc[i][j] = 0ull;

    for (int k0 = 0; k0 < HW; k0 += 16) {
        #pragma unroll
        for (int l = 0; l < 4; l++) {
            int idx = t + l * 256;
            int row = idx >> 4;
            int col = idx & 15;
            As[row][col] = feat[(size_t)(ti * 64 + row) * HW + k0 + col];
            Bs[row][col] = feat[(size_t)(tj * 64 + row) * HW + k0 + col];
        }
        __syncthreads();

        #pragma unroll
        for (int kk = 0; kk < 16; kk += 2) {
            unsigned long long a2[4], b2[4];
            #pragma unroll
            for (int i = 0; i < 4; i++)
                a2[i] = *reinterpret_cast<const unsigned long long*>(&As[ty * 4 + i][kk]);
            #pragma unroll
            for (int j = 0; j < 4; j++)
                b2[j] = *reinterpret_cast<const unsigned long long*>(&Bs[tx * 4 + j][kk]);
            #pragma unroll
            for (int i = 0; i < 4; i++)
                #pragma unroll
                for (int j = 0; j < 4; j++)
                    ffma2(acc[i][j], a2[i], b2[j]);
        }
        __syncthreads();
    }

    #pragma unroll
    for (int i = 0; i < 4; i++) {
        int gi = ti * 64 + ty * 4 + i;
        #pragma unroll
        for (int j = 0; j < 4; j++) {
            int gj = tj * 64 + tx * 4 + j;
            if (gi <= gj) {
                int off = gi * DIMC - (gi * (gi - 1)) / 2 + (gj - gi);
                g[(size_t)b * GRAMD + off] = fold_f32x2(acc[i][j]);
            }
        }
    }
}

// ---------------------------------------------------------------------------
// Fused GEMM + bias + leaky-relu, f32x2 FMAs + register prefetch of W.
// out[b][n] = lrelu(sum_k in[b][k]*W[n][k] + bias[n]).  M = 32 batches.
// Each warp: 4 n x 8 b, lanes slice K (float4 -> 2x f32x2 per operand).
// Block = 256 = 8 warps = 2 n-groups x 4 b-groups -> 8 n, 32 b per block.
// W (DRAM-resident, read once) is prefetched one K-iteration ahead so the
// ~600-cycle DRAM latency overlaps the previous iteration's FFMA2 block.
// ---------------------------------------------------------------------------
template <int K, int N>
__global__ __launch_bounds__(256, 2)
void gemm_lrelu(const float* __restrict__ in, const float* __restrict__ W,
                const float* __restrict__ bias, float* __restrict__ out)
{
    int t    = threadIdx.x;
    int lane = t & 31;
    int wid  = t >> 5;
    int ng   = wid >> 2;          // 0..1
    int bg   = wid & 3;           // 0..3
    int n0   = blockIdx.x * 8 + ng * 4;
    int b0   = bg * 8;

    unsigned long long acc[4][8];
    #pragma unroll
    for (int i = 0; i < 4; i++)
        #pragma unroll
        for (int j = 0; j < 8; j++) acc[i][j] = 0ull;

    const int klane = lane * 4;

    // Prime: load W for k0 = 0 (klane < 128 <= K always)
    ulonglong2 wc[4];
    #pragma unroll
    for (int i = 0; i < 4; i++)
        wc[i] = *reinterpret_cast<const ulonglong2*>(W + (size_t)(n0 + i) * K + klane);

    for (int k0 = 0; k0 < K; k0 += 128) {
        int kk = k0 + klane;
        int kn = kk + 128;

        // Prefetch next iteration's W (guard == next-iter lane validity)
        ulonglong2 wn[4];
        if (kn < K) {
            #pragma unroll
            for (int i = 0; i < 4; i++)
                wn[i] = *reinterpret_cast<const ulonglong2*>(W + (size_t)(n0 + i) * K + kn);
        }

        if (kk < K) {
            // First half of batches
            ulonglong2 g2[4];
            #pragma unroll
            for (int j = 0; j < 4; j++)
                g2[j] = *reinterpret_cast<const ulonglong2*>(in + (size_t)(b0 + j) * K + kk);
            #pragma unroll
            for (int i = 0; i < 4; i++)
                #pragma unroll
                for (int j = 0; j < 4; j++) {
                    ffma2(acc[i][j], wc[i].x, g2[j].x);
                    ffma2(acc[i][j], wc[i].y, g2[j].y);
                }
            // Second half of batches
            #pragma unroll
            for (int j = 0; j < 4; j++)
                g2[j] = *reinterpret_cast<const ulonglong2*>(in + (size_t)(b0 + 4 + j) * K + kk);
            #pragma unroll
            for (int i = 0; i < 4; i++)
                #pragma unroll
                for (int j = 0; j < 4; j++) {
                    ffma2(acc[i][4 + j], wc[i].x, g2[j].x);
                    ffma2(acc[i][4 + j], wc[i].y, g2[j].y);
                }
        }

        #pragma unroll
        for (int i = 0; i < 4; i++) wc[i] = wn[i];
    }

    // Fold dual lanes, then cross-lane (split-K) butterfly reduction
    float accf[4][8];
    #pragma unroll
    for (int i = 0; i < 4; i++)
        #pragma unroll
        for (int j = 0; j < 8; j++) accf[i][j] = fold_f32x2(acc[i][j]);

    #pragma unroll
    for (int off = 16; off > 0; off >>= 1) {
        #pragma unroll
        for (int i = 0; i < 4; i++)
            #pragma unroll
            for (int j = 0; j < 8; j++)
                accf[i][j] += __shfl_xor_sync(0xffffffffu, accf[i][j], off);
    }

    if (lane == 0) {
        #pragma unroll
        for (int i = 0; i < 4; i++) {
            float bi = bias[n0 + i];
            #pragma unroll
            for (int j = 0; j < 8; j++) {
                float v = accf[i][j] + bi;
                v = (v > 0.0f) ? v : 0.01f * v;
                out[(size_t)(b0 + j) * N + (n0 + i)] = v;
            }
        }
    }
}

// ---------------------------------------------------------------------------
// Layer 3: N=64. grid=64 (one block per n), block=512 = 16 warps:
// 4 k-warp-groups x 4 b-groups (8 batches each). smem reduce across k-groups.
// ---------------------------------------------------------------------------
#define N2_F4 (N2 / 4)   // 1158 float4s per row
__global__ __launch_bounds__(512)
void gemm3_lrelu(const float* __restrict__ in, const float* __restrict__ W,
                 const float* __restrict__ bias, float* __restrict__ out)
{
    __shared__ float red[4][32];   // [k-warp-group][batch]

    int n    = blockIdx.x;               // 0..63
    int t    = threadIdx.x;
    int lane = t & 31;
    int wid  = t >> 5;                   // 0..15
    int bg   = wid & 3;                  // b-group: batches bg*8 .. bg*8+7
    int kw   = wid >> 2;                 // k-warp-group 0..3

    const float4* wrow = reinterpret_cast<const float4*>(W + (size_t)n * N2);

    float acc[8];
    #pragma unroll
    for (int j = 0; j < 8; j++) acc[j] = 0.0f;

    for (int idx4 = kw * 32 + lane; idx4 < N2_F4; idx4 += 128) {
        float4 w = wrow[idx4];
        #pragma unroll
        for (int j = 0; j < 8; j++) {
            float4 gv = reinterpret_cast<const float4*>(in + (size_t)(bg * 8 + j) * N2)[idx4];
            acc[j] += w.x * gv.x + w.y * gv.y + w.z * gv.z + w.w * gv.w;
        }
    }

    #pragma unroll
    for (int off = 16; off > 0; off >>= 1)
        #pragma unroll
        for (int j = 0; j < 8; j++)
            acc[j] += __shfl_xor_sync(0xffffffffu, acc[j], off);

    if (lane < 8)   // lane j stores batch bg*8+j... use lane==0 owner writes all 8
        ;
    if (lane == 0) {
        #pragma unroll
        for (int j = 0; j < 8; j++)
            red[kw][bg * 8 + j] = acc[j];
    }
    __syncthreads();

    if (t < 32) {
        float s = red[0][t] + red[1][t] + red[2][t] + red[3][t] + bias[n];
        s = (s > 0.0f) ? s : 0.01f * s;
        out[(size_t)t * N3 + n] = s;
    }
}

// ---------------------------------------------------------------------------
// Final: L2-normalize h3 (per-sample over 64), dot with W4, +b4, sigmoid.
// ---------------------------------------------------------------------------
__global__ void final_kernel(const float* __restrict__ h3, const float* __restrict__ W4,
                             const float* __restrict__ b4, float* __restrict__ out)
{
    int b    = threadIdx.x >> 5;
    int lane = threadIdx.x & 31;

    float v0 = h3[b * 64 + lane * 2];
    float v1 = h3[b * 64 + lane * 2 + 1];

    float ss = v0 * v0 + v1 * v1;
    #pragma unroll
    for (int off = 16; off > 0; off >>= 1)
        ss += __shfl_xor_sync(0xffffffffu, ss, off);

    float denom = fmaxf(sqrtf(ss), 1e-12f);

    float d = v0 * W4[lane * 2] + v1 * W4[lane * 2 + 1];
    #pragma unroll
    for (int off = 16; off > 0; off >>= 1)
        d += __shfl_xor_sync(0xffffffffu, d, off);

    if (lane == 0) {
        float logit = d / denom + b4[0];
        out[b] = 1.0f / (1.0f + expf(-logit));
    }
}

// ---------------------------------------------------------------------------
// Launch.  Inputs (metadata order): x, W1, b1, W2, b2, W3, b3, W4, b4 (fp32)
// ---------------------------------------------------------------------------
extern "C" void kernel_launch(void* const* d_in, const int* in_sizes, int n_in,
                              void* d_out, int out_size)
{
    const float* x  = (const float*)d_in[0];
    const float* W1 = (const float*)d_in[1];
    const float* b1 = (const float*)d_in[2];
    const float* W2 = (const float*)d_in[3];
    const float* b2 = (const float*)d_in[4];
    const float* W3 = (const float*)d_in[5];
    const float* b3 = (const float*)d_in[6];
    const float* W4 = (const float*)d_in[7];
    const float* b4 = (const float*)d_in[8];
    float* out = (float*)d_out;

    float *g, *h1, *h2, *h3;
    cudaGetSymbolAddress((void**)&g,  g_buf);
    cudaGetSymbolAddress((void**)&h1, h1_buf);
    cudaGetSymbolAddress((void**)&h2, h2_buf);
    cudaGetSymbolAddress((void**)&h3, h3_buf);

    gram_kernel<<<dim3(6, BATCH), 256>>>(x, g);
    gemm_lrelu<GRAMD, N1><<<N1 / 8, 256>>>(g,  W1, b1, h1);
    gemm_lrelu<N1,    N2><<<N2 / 8, 256>>>(h1, W2, b2, h2);
    gemm3_lrelu<<<N3, 512>>>(h2, W3, b3, h3);
    final_kernel<<<1, 1024>>>(h3, W4, b4, out);
}

// round 6
// speedup vs baseline: 1.6001x; 1.6001x over previous
#include <cuda_runtime.h>
#include <math.h>

// Shapes
#define DIMC 192
#define HW   1024
#define BATCH 32
#define GRAMD 18528   // 192*193/2
#define N1 9264
#define N2 4632
#define N3 64

// Scratch (device globals: no allocation allowed in kernel_launch)
__device__ float g_buf[BATCH * GRAMD];
__device__ float h1_buf[BATCH * N1];
__device__ float h2_buf[BATCH * N2];
__device__ float h3_buf[BATCH * N3];

// Packed f32x2 FMA: d = a*b + d  (two independent fp32 lanes per issue slot)
__device__ __forceinline__ void ffma2(unsigned long long& d,
                                      unsigned long long a,
                                      unsigned long long b)
{
    asm("fma.rn.f32x2 %0, %1, %2, %0;" : "+l"(d) : "l"(a), "l"(b));
}

__device__ __forceinline__ unsigned long long dup2(float v)
{
    unsigned long long r;
    asm("mov.b64 %0, {%1, %1};" : "=l"(r) : "f"(v));
    return r;
}

// ---------------------------------------------------------------------------
// Kernel 1: per-sample Gram upper-triangle features (known-good version).
// grid = (6 tile-pairs, 32 batch), block = 256 threads (16x16), 4x4 micro-tile.
// ---------------------------------------------------------------------------
__global__ void gram_kernel(const float* __restrict__ x, float* __restrict__ g)
{
    __shared__ float As[64][17];
    __shared__ float Bs[64][17];

    const int TI[6] = {0, 0, 0, 1, 1, 2};
    const int TJ[6] = {0, 1, 2, 1, 2, 2};

    int pair = blockIdx.x;
    int b    = blockIdx.y;
    int ti = TI[pair], tj = TJ[pair];

    const float* feat = x + (size_t)b * DIMC * HW;

    int t  = threadIdx.x;
    int ty = t >> 4;
    int tx = t & 15;

    float acc[4][4];
    #pragma unroll
    for (int i = 0; i < 4; i++)
        #pragma unroll
        for (int j = 0; j < 4; j++) acc[i][j] = 0.0f;

    for (int k0 = 0; k0 < HW; k0 += 16) {
        #pragma unroll
        for (int l = 0; l < 4; l++) {
            int idx = t + l * 256;
            int row = idx >> 4;
            int col = idx & 15;
            As[row][col] = feat[(size_t)(ti * 64 + row) * HW + k0 + col];
            Bs[row][col] = feat[(size_t)(tj * 64 + row) * HW + k0 + col];
        }
        __syncthreads();

        #pragma unroll
        for (int kk = 0; kk < 16; kk++) {
            float a[4], bb[4];
            #pragma unroll
            for (int i = 0; i < 4; i++) a[i]  = As[ty * 4 + i][kk];
            #pragma unroll
            for (int j = 0; j < 4; j++) bb[j] = Bs[tx * 4 + j][kk];
            #pragma unroll
            for (int i = 0; i < 4; i++)
                #pragma unroll
                for (int j = 0; j < 4; j++)
                    acc[i][j] += a[i] * bb[j];
        }
        __syncthreads();
    }

    #pragma unroll
    for (int i = 0; i < 4; i++) {
        int gi = ti * 64 + ty * 4 + i;
        #pragma unroll
        for (int j = 0; j < 4; j++) {
            int gj = tj * 64 + tx * 4 + j;
            if (gi <= gj) {
                int off = gi * DIMC - (gi * (gi - 1)) / 2 + (gj - gi);
                g[(size_t)b * GRAMD + off] = acc[i][j];
            }
        }
    }
}

// ---------------------------------------------------------------------------
// Smem double-buffered GEMM + bias + leaky-relu.
// out[b][n] = lrelu(sum_k in[b][k] * W[n][k] + bias[n]),  b = 0..31.
// Block = 256 threads: 16 n-threads x 16 b-threads.
// Thread tile: NT n-values x 2 batches. Ntile = 16*NT, Mtile = 32, Kchunk = 48.
// Both buffers in smem, transposed to [k][n] / [k][b] for contiguous reads.
// W is streamed from DRAM exactly once; activations come from L2/smem.
// No split-K: accumulators stay in 2*NT registers (f32x2-packed along n).
// ---------------------------------------------------------------------------
template <int K, int N, int NT>
__global__ __launch_bounds__(256)
void gemm_tile(const float* __restrict__ in, const float* __restrict__ W,
               const float* __restrict__ bias, float* __restrict__ out)
{
    constexpr int NTILE = NT * 16;
    constexpr int KC    = 48;
    constexpr int WPAD  = NTILE + 4;          // rows 16B-aligned
    constexpr int KPR   = KC / 4;             // float4 per k-row = 12
    constexpr int WF4   = NTILE * KPR;        // W float4 per chunk
    constexpr int GF4   = 32 * KPR;           // 384
    constexpr int WREG  = (WF4 + 255) / 256;
    constexpr int GREG  = (GF4 + 255) / 256;

    __shared__ float Ws[2][KC][WPAD];
    __shared__ float Gs[2][KC][34];           // 34: 8B-aligned rows, low conflict

    int tid  = threadIdx.x;
    int nt   = tid & 15;
    int bt   = tid >> 4;
    int n0b  = blockIdx.x * NTILE;
    int nloc = nt * NT;
    int b0   = bt * 2;

    unsigned long long acc[2][NT / 2];
    #pragma unroll
    for (int bi = 0; bi < 2; bi++)
        #pragma unroll
        for (int np = 0; np < NT / 2; np++) acc[bi][np] = 0ull;

    float4 wreg[WREG];
    float4 greg[GREG];

    // ---- load chunk k0 into registers ----
    auto ldg_chunk = [&](int k0) {
        #pragma unroll
        for (int r = 0; r < WREG; r++) {
            int f = tid + r * 256;
            if (f < WF4) {
                int n  = f / KPR;
                int kq = f % KPR;
                int row = n0b + n;
                if (row >= N) row = N - 1;     // safe duplicate read; store guarded
                wreg[r] = *reinterpret_cast<const float4*>(
                    W + (size_t)row * K + k0 + kq * 4);
            }
        }
        #pragma unroll
        for (int r = 0; r < GREG; r++) {
            int f = tid + r * 256;
            if (f < GF4) {
                int b  = f / KPR;
                int kq = f % KPR;
                greg[r] = *reinterpret_cast<const float4*>(
                    in + (size_t)b * K + k0 + kq * 4);
            }
        }
    };

    // ---- store registers into smem buffer s (transposed) ----
    auto sts_chunk = [&](int s) {
        #pragma unroll
        for (int r = 0; r < WREG; r++) {
            int f = tid + r * 256;
            if (f < WF4) {
                int n  = f / KPR;
                int kq = f % KPR;
                Ws[s][kq * 4 + 0][n] = wreg[r].x;
                Ws[s][kq * 4 + 1][n] = wreg[r].y;
                Ws[s][kq * 4 + 2][n] = wreg[r].z;
                Ws[s][kq * 4 + 3][n] = wreg[r].w;
            }
        }
        #pragma unroll
        for (int r = 0; r < GREG; r++) {
            int f = tid + r * 256;
            if (f < GF4) {
                int b  = f / KPR;
                int kq = f % KPR;
                Gs[s][kq * 4 + 0][b] = greg[r].x;
                Gs[s][kq * 4 + 1][b] = greg[r].y;
                Gs[s][kq * 4 + 2][b] = greg[r].z;
                Gs[s][kq * 4 + 3][b] = greg[r].w;
            }
        }
    };

    const int nchunks = K / KC;   // K divisible by 48 for both layers

    ldg_chunk(0);
    sts_chunk(0);
    __syncthreads();

    for (int c = 0; c < nchunks; c++) {
        int s = c & 1;
        if (c + 1 < nchunks) ldg_chunk((c + 1) * KC);

        #pragma unroll 12
        for (int k = 0; k < KC; k++) {
            float2 gv = *reinterpret_cast<const float2*>(&Gs[s][k][b0]);
            unsigned long long gx = dup2(gv.x);
            unsigned long long gy = dup2(gv.y);
            #pragma unroll
            for (int np = 0; np < NT / 2; np++) {
                unsigned long long w =
                    *reinterpret_cast<const unsigned long long*>(&Ws[s][k][nloc + np * 2]);
                ffma2(acc[0][np], w, gx);
                ffma2(acc[1][np], w, gy);
            }
        }

        if (c + 1 < nchunks) sts_chunk(s ^ 1);
        __syncthreads();
    }

    // ---- epilogue: bias + leaky-relu, guarded stores ----
    #pragma unroll
    for (int bi = 0; bi < 2; bi++) {
        int b = b0 + bi;
        #pragma unroll
        for (int np = 0; np < NT / 2; np++) {
            float2 v2 = *reinterpret_cast<float2*>(&acc[bi][np]);
            #pragma unroll
            for (int i = 0; i < 2; i++) {
                int n = n0b + nloc + np * 2 + i;
                if (n < N) {
                    float v = (i == 0 ? v2.x : v2.y) + bias[n];
                    v = (v > 0.0f) ? v : 0.01f * v;
                    out[(size_t)b * N + n] = v;
                }
            }
        }
    }
}

// ---------------------------------------------------------------------------
// Layer 3: N=64. grid=64 (one block per n), block=512 = 16 warps:
// 4 k-warp-groups x 4 b-groups (8 batches each). smem reduce across k-groups.
// ---------------------------------------------------------------------------
#define N2_F4 (N2 / 4)   // 1158 float4s per row
__global__ __launch_bounds__(512)
void gemm3_lrelu(const float* __restrict__ in, const float* __restrict__ W,
                 const float* __restrict__ bias, float* __restrict__ out)
{
    __shared__ float red[4][32];

    int n    = blockIdx.x;
    int t    = threadIdx.x;
    int lane = t & 31;
    int wid  = t >> 5;
    int bg   = wid & 3;
    int kw   = wid >> 2;

    const float4* wrow = reinterpret_cast<const float4*>(W + (size_t)n * N2);

    float acc[8];
    #pragma unroll
    for (int j = 0; j < 8; j++) acc[j] = 0.0f;

    for (int idx4 = kw * 32 + lane; idx4 < N2_F4; idx4 += 128) {
        float4 w = wrow[idx4];
        #pragma unroll
        for (int j = 0; j < 8; j++) {
            float4 gv = reinterpret_cast<const float4*>(in + (size_t)(bg * 8 + j) * N2)[idx4];
            acc[j] += w.x * gv.x + w.y * gv.y + w.z * gv.z + w.w * gv.w;
        }
    }

    #pragma unroll
    for (int off = 16; off > 0; off >>= 1)
        #pragma unroll
        for (int j = 0; j < 8; j++)
            acc[j] += __shfl_xor_sync(0xffffffffu, acc[j], off);

    if (lane == 0) {
        #pragma unroll
        for (int j = 0; j < 8; j++)
            red[kw][bg * 8 + j] = acc[j];
    }
    __syncthreads();

    if (t < 32) {
        float s = red[0][t] + red[1][t] + red[2][t] + red[3][t] + bias[n];
        s = (s > 0.0f) ? s : 0.01f * s;
        out[(size_t)t * N3 + n] = s;
    }
}

// ---------------------------------------------------------------------------
// Final: L2-normalize h3 (per-sample over 64), dot with W4, +b4, sigmoid.
// ---------------------------------------------------------------------------
__global__ void final_kernel(const float* __restrict__ h3, const float* __restrict__ W4,
                             const float* __restrict__ b4, float* __restrict__ out)
{
    int b    = threadIdx.x >> 5;
    int lane = threadIdx.x & 31;

    float v0 = h3[b * 64 + lane * 2];
    float v1 = h3[b * 64 + lane * 2 + 1];

    float ss = v0 * v0 + v1 * v1;
    #pragma unroll
    for (int off = 16; off > 0; off >>= 1)
        ss += __shfl_xor_sync(0xffffffffu, ss, off);

    float denom = fmaxf(sqrtf(ss), 1e-12f);

    float d = v0 * W4[lane * 2] + v1 * W4[lane * 2 + 1];
    #pragma unroll
    for (int off = 16; off > 0; off >>= 1)
        d += __shfl_xor_sync(0xffffffffu, d, off);

    if (lane == 0) {
        float logit = d / denom + b4[0];
        out[b] = 1.0f / (1.0f + expf(-logit));
    }
}

// ---------------------------------------------------------------------------
// Launch.  Inputs (metadata order): x, W1, b1, W2, b2, W3, b3, W4, b4 (fp32)
// ---------------------------------------------------------------------------
extern "C" void kernel_launch(void* const* d_in, const int* in_sizes, int n_in,
                              void* d_out, int out_size)
{
    const float* x  = (const float*)d_in[0];
    const float* W1 = (const float*)d_in[1];
    const float* b1 = (const float*)d_in[2];
    const float* W2 = (const float*)d_in[3];
    const float* b2 = (const float*)d_in[4];
    const float* W3 = (const float*)d_in[5];
    const float* b3 = (const float*)d_in[6];
    const float* W4 = (const float*)d_in[7];
    const float* b4 = (const float*)d_in[8];
    float* out = (float*)d_out;

    float *g, *h1, *h2, *h3;
    cudaGetSymbolAddress((void**)&g,  g_buf);
    cudaGetSymbolAddress((void**)&h1, h1_buf);
    cudaGetSymbolAddress((void**)&h2, h2_buf);
    cudaGetSymbolAddress((void**)&h3, h3_buf);

    gram_kernel<<<dim3(6, BATCH), 256>>>(x, g);

    // GEMM1: Ntile=64 -> ceil(9264/64)=145 blocks (~1 full wave)
    gemm_tile<GRAMD, N1, 4><<<(N1 + 63) / 64, 256>>>(g, W1, b1, h1);
    // GEMM2: Ntile=32 -> ceil(4632/32)=145 blocks (~1 full wave)
    gemm_tile<N1, N2, 2><<<(N2 + 31) / 32, 256>>>(h1, W2, b2, h2);

    gemm3_lrelu<<<N3, 512>>>(h2, W3, b3, h3);
    final_kernel<<<1, 1024>>>(h3, W4, b4, out);
}

// round 9
// speedup vs baseline: 1.9133x; 1.1957x over previous
#include <cuda_runtime.h>
#include <math.h>
#include <stdint.h>

// Shapes
#define DIMC 192
#define HW   1024
#define BATCH 32
#define GRAMD 18528   // 192*193/2
#define N1 9264
#define N2 4632
#define N3 64

// Scratch (device globals: no allocation allowed in kernel_launch)
__device__ float g_buf[BATCH * GRAMD];
__device__ float h1_buf[BATCH * N1];
__device__ float h2_buf[BATCH * N2];
__device__ float h3p_buf[4 * BATCH * N3];   // split-K partials for layer 3

// ---------------------------------------------------------------------------
// helpers
// ---------------------------------------------------------------------------
__device__ __forceinline__ void ffma2(unsigned long long& d,
                                      unsigned long long a,
                                      unsigned long long b)
{
    asm("fma.rn.f32x2 %0, %1, %2, %0;" : "+l"(d) : "l"(a), "l"(b));
}

__device__ __forceinline__ float fold_f32x2(unsigned long long v)
{
    float2 f = *reinterpret_cast<float2*>(&v);
    return f.x + f.y;
}

__device__ __forceinline__ uint32_t tf32_of(float f)
{
    uint32_t r;
    asm("cvt.rna.tf32.f32 %0, %1;" : "=r"(r) : "f"(f));
    return r;
}

__device__ __forceinline__ void cp_async16(uint32_t smem_addr, const void* gptr)
{
    asm volatile("cp.async.ca.shared.global [%0], [%1], 16;"
                 :: "r"(smem_addr), "l"(gptr));
}

__device__ __forceinline__ void mma_tf32(float* d, const uint32_t* a,
                                         uint32_t b0, uint32_t b1)
{
    asm volatile(
        "mma.sync.aligned.m16n8k8.row.col.f32.tf32.tf32.f32 "
        "{%0,%1,%2,%3}, {%4,%5,%6,%7}, {%8,%9}, {%0,%1,%2,%3};"
        : "+f"(d[0]), "+f"(d[1]), "+f"(d[2]), "+f"(d[3])
        : "r"(a[0]), "r"(a[1]), "r"(a[2]), "r"(a[3]), "r"(b0), "r"(b1));
}

// ---------------------------------------------------------------------------
// Kernel 1: per-sample Gram upper-triangle features (f32x2 inner loop; proven).
// grid = (6 tile-pairs, 32 batch), block = 256 threads (16x16), 4x4 micro-tile.
// ---------------------------------------------------------------------------
__global__ void gram_kernel(const float* __restrict__ x, float* __restrict__ g)
{
    __shared__ float As[64][18];
    __shared__ float Bs[64][18];

    const int TI[6] = {0, 0, 0, 1, 1, 2};
    const int TJ[6] = {0, 1, 2, 1, 2, 2};

    int pair = blockIdx.x;
    int b    = blockIdx.y;
    int ti = TI[pair], tj = TJ[pair];

    const float* feat = x + (size_t)b * DIMC * HW;

    int t  = threadIdx.x;
    int ty = t >> 4;
    int tx = t & 15;

    unsigned long long acc[4][4];
    #pragma unroll
    for (int i = 0; i < 4; i++)
        #pragma unroll
        for (int j = 0; j < 4; j++) acc[i][j] = 0ull;

    for (int k0 = 0; k0 < HW; k0 += 16) {
        #pragma unroll
        for (int l = 0; l < 4; l++) {
            int idx = t + l * 256;
            int row = idx >> 4;
            int col = idx & 15;
            As[row][col] = feat[(size_t)(ti * 64 + row) * HW + k0 + col];
            Bs[row][col] = feat[(size_t)(tj * 64 + row) * HW + k0 + col];
        }
        __syncthreads();

        #pragma unroll
        for (int kk = 0; kk < 16; kk += 2) {
            unsigned long long a2[4], b2[4];
            #pragma unroll
            for (int i = 0; i < 4; i++)
                a2[i] = *reinterpret_cast<const unsigned long long*>(&As[ty * 4 + i][kk]);
            #pragma unroll
            for (int j = 0; j < 4; j++)
                b2[j] = *reinterpret_cast<const unsigned long long*>(&Bs[tx * 4 + j][kk]);
            #pragma unroll
            for (int i = 0; i < 4; i++)
                #pragma unroll
                for (int j = 0; j < 4; j++)
                    ffma2(acc[i][j], a2[i], b2[j]);
        }
        __syncthreads();
    }

    #pragma unroll
    for (int i = 0; i < 4; i++) {
        int gi = ti * 64 + ty * 4 + i;
        #pragma unroll
        for (int j = 0; j < 4; j++) {
            int gj = tj * 64 + tx * 4 + j;
            if (gi <= gj) {
                int off = gi * DIMC - (gi * (gi - 1)) / 2 + (gj - gi);
                g[(size_t)b * GRAMD + off] = fold_f32x2(acc[i][j]);
            }
        }
    }
}

// ---------------------------------------------------------------------------
// TF32 tensor-core GEMM + bias + leaky-relu.
// out[b][n] = lrelu(sum_k in[b][k] * W[n][k] + bias[n]),  b = 0..31.
// mma.m16n8k8: M-dim = n (W rows, K-contig = row), N-dim = batch (g rows,
// K-contig = col). Block = 128 threads = 4 warps; warp w owns n rows
// [n0b + 16w, +16), all 32 batches (4 n8 tiles). Mtile = 64, KC = 48
// (6 k8 steps), cp.async double-buffered smem.
// ---------------------------------------------------------------------------
template <int K, int N>
__global__ __launch_bounds__(128)
void gemm_mma(const float* __restrict__ in, const float* __restrict__ W,
              const float* __restrict__ bias, float* __restrict__ out)
{
    constexpr int KC = 48;
    constexpr int PITCH = 52;           // floats; 208B row, 16B-aligned, conflict-free frags
    constexpr int NCH = K / KC;         // 386 / 193 (exact for both layers)

    __shared__ float Ws[2][64 * PITCH];
    __shared__ float Gs[2][32 * PITCH];

    int tid  = threadIdx.x;
    int lane = tid & 31;
    int warp = tid >> 5;                // 0..3
    int gid  = lane >> 2;               // 0..7
    int tig  = lane & 3;                // 0..3
    int n0b  = blockIdx.x * 64;
    int nw   = warp * 16;

    float d[4][4];                      // [btile][reg]
    #pragma unroll
    for (int bt = 0; bt < 4; bt++)
        #pragma unroll
        for (int r = 0; r < 4; r++) d[bt][r] = 0.0f;

    uint32_t ws_base[2], gs_base[2];
    #pragma unroll
    for (int s = 0; s < 2; s++) {
        ws_base[s] = (uint32_t)__cvta_generic_to_shared(&Ws[s][0]);
        gs_base[s] = (uint32_t)__cvta_generic_to_shared(&Gs[s][0]);
    }

    auto issue = [&](int c) {
        int k0 = c * KC;
        int s  = c & 1;
        // W: 64 rows x 12 float4 = 768 ops, 6 per thread
        #pragma unroll
        for (int r = 0; r < 6; r++) {
            int f   = tid + r * 128;
            int row = f / 12;
            int q   = f % 12;
            int grow = n0b + row;
            if (grow >= N) grow = N - 1;             // safe duplicate; stores guarded
            cp_async16(ws_base[s] + (uint32_t)(row * PITCH + q * 4) * 4,
                       W + (size_t)grow * K + k0 + q * 4);
        }
        // g: 32 rows x 12 float4 = 384 ops, 3 per thread
        #pragma unroll
        for (int r = 0; r < 3; r++) {
            int f   = tid + r * 128;
            int row = f / 12;
            int q   = f % 12;
            cp_async16(gs_base[s] + (uint32_t)(row * PITCH + q * 4) * 4,
                       in + (size_t)row * K + k0 + q * 4);
        }
        asm volatile("cp.async.commit_group;");
    };

    issue(0);

    for (int c = 0; c < NCH; c++) {
        if (c + 1 < NCH) {
            issue(c + 1);
            asm volatile("cp.async.wait_group 1;");
        } else {
            asm volatile("cp.async.wait_group 0;");
        }
        __syncthreads();

        int s = c & 1;
        const float* ws = &Ws[s][0];
        const float* gs = &Gs[s][0];

        #pragma unroll
        for (int k8 = 0; k8 < 6; k8++) {
            int kk = k8 * 8;
            uint32_t a[4];
            a[0] = tf32_of(ws[(nw + gid) * PITCH + kk + tig]);
            a[1] = tf32_of(ws[(nw + gid + 8) * PITCH + kk + tig]);
            a[2] = tf32_of(ws[(nw + gid) * PITCH + kk + tig + 4]);
            a[3] = tf32_of(ws[(nw + gid + 8) * PITCH + kk + tig + 4]);
            #pragma unroll
            for (int bt = 0; bt < 4; bt++) {
                uint32_t b0 = tf32_of(gs[(bt * 8 + gid) * PITCH + kk + tig]);
                uint32_t b1 = tf32_of(gs[(bt * 8 + gid) * PITCH + kk + tig + 4]);
                mma_tf32(d[bt], a, b0, b1);
            }
        }
        __syncthreads();
    }

    // Epilogue: c0=(gid,2tig) c1=(gid,2tig+1) c2=(gid+8,2tig) c3=(gid+8,2tig+1)
    #pragma unroll
    for (int bt = 0; bt < 4; bt++) {
        int b  = bt * 8 + 2 * tig;
        int n_0 = n0b + nw + gid;
        int n_1 = n_0 + 8;
        if (n_0 < N) {
            float bi = bias[n_0];
            float v0 = d[bt][0] + bi; v0 = (v0 > 0.f) ? v0 : 0.01f * v0;
            float v1 = d[bt][1] + bi; v1 = (v1 > 0.f) ? v1 : 0.01f * v1;
            out[(size_t)b * N + n_0]       = v0;
            out[(size_t)(b + 1) * N + n_0] = v1;
        }
        if (n_1 < N) {
            float bi = bias[n_1];
            float v2 = d[bt][2] + bi; v2 = (v2 > 0.f) ? v2 : 0.01f * v2;
            float v3 = d[bt][3] + bi; v3 = (v3 > 0.f) ? v3 : 0.01f * v3;
            out[(size_t)b * N + n_1]       = v2;
            out[(size_t)(b + 1) * N + n_1] = v3;
        }
    }
}

// ---------------------------------------------------------------------------
// Layer 3, split-K partials: grid (4 kslices, 64 n), block 256 (8 warps x 4 b).
// part[ks][b][n] = partial dot over kslice. No bias/activation here.
// ---------------------------------------------------------------------------
#define N2_F4 (N2 / 4)   // 1158
__global__ __launch_bounds__(256)
void gemm3_partial(const float* __restrict__ in, const float* __restrict__ W,
                   float* __restrict__ part)
{
    int ks   = blockIdx.x;               // 0..3
    int n    = blockIdx.y;               // 0..63
    int lane = threadIdx.x & 31;
    int warp = threadIdx.x >> 5;         // 0..7 -> batches warp*4..+3

    int k4b = ks * 290;
    int k4e = min(N2_F4, k4b + 290);

    const float4* wrow = reinterpret_cast<const float4*>(W + (size_t)n * N2);

    float acc[4] = {0.f, 0.f, 0.f, 0.f};

    for (int i = k4b + lane; i < k4e; i += 32) {
        float4 w = wrow[i];
        #pragma unroll
        for (int j = 0; j < 4; j++) {
            float4 gv = reinterpret_cast<const float4*>(in + (size_t)(warp * 4 + j) * N2)[i];
            acc[j] += w.x * gv.x + w.y * gv.y + w.z * gv.z + w.w * gv.w;
        }
    }

    #pragma unroll
    for (int off = 16; off > 0; off >>= 1)
        #pragma unroll
        for (int j = 0; j < 4; j++)
            acc[j] += __shfl_xor_sync(0xffffffffu, acc[j], off);

    if (lane == 0) {
        #pragma unroll
        for (int j = 0; j < 4; j++)
            part[((size_t)ks * BATCH + warp * 4 + j) * N3 + n] = acc[j];
    }
}

// ---------------------------------------------------------------------------
// Final: reduce split-K partials, + b3, leaky-relu, L2-normalize, dot W4,
// + b4, sigmoid.  32 warps, warp = batch sample; lane owns 2 of 64 dims.
// ---------------------------------------------------------------------------
__global__ void final_kernel(const float* __restrict__ part,
                             const float* __restrict__ b3,
                             const float* __restrict__ W4,
                             const float* __restrict__ b4,
                             float* __restrict__ out)
{
    int b    = threadIdx.x >> 5;
    int lane = threadIdx.x & 31;
    int i0 = lane * 2, i1 = lane * 2 + 1;

    float v0 = b3[i0], v1 = b3[i1];
    #pragma unroll
    for (int s = 0; s < 4; s++) {
        v0 += part[((size_t)s * BATCH + b) * N3 + i0];
        v1 += part[((size_t)s * BATCH + b) * N3 + i1];
    }
    v0 = (v0 > 0.f) ? v0 : 0.01f * v0;
    v1 = (v1 > 0.f) ? v1 : 0.01f * v1;

    float ss = v0 * v0 + v1 * v1;
    #pragma unroll
    for (int off = 16; off > 0; off >>= 1)
        ss += __shfl_xor_sync(0xffffffffu, ss, off);

    float denom = fmaxf(sqrtf(ss), 1e-12f);

    float dsum = v0 * W4[i0] + v1 * W4[i1];
    #pragma unroll
    for (int off = 16; off > 0; off >>= 1)
        dsum += __shfl_xor_sync(0xffffffffu, dsum, off);

    if (lane == 0) {
        float logit = dsum / denom + b4[0];
        out[b] = 1.0f / (1.0f + expf(-logit));
    }
}

// ---------------------------------------------------------------------------
// Launch.  Inputs (metadata order): x, W1, b1, W2, b2, W3, b3, W4, b4 (fp32)
// ---------------------------------------------------------------------------
extern "C" void kernel_launch(void* const* d_in, const int* in_sizes, int n_in,
                              void* d_out, int out_size)
{
    const float* x  = (const float*)d_in[0];
    const float* W1 = (const float*)d_in[1];
    const float* b1 = (const float*)d_in[2];
    const float* W2 = (const float*)d_in[3];
    const float* b2 = (const float*)d_in[4];
    const float* W3 = (const float*)d_in[5];
    const float* b3 = (const float*)d_in[6];
    const float* W4 = (const float*)d_in[7];
    const float* b4 = (const float*)d_in[8];
    float* out = (float*)d_out;

    float *g, *h1, *h2, *h3p;
    cudaGetSymbolAddress((void**)&g,   g_buf);
    cudaGetSymbolAddress((void**)&h1,  h1_buf);
    cudaGetSymbolAddress((void**)&h2,  h2_buf);
    cudaGetSymbolAddress((void**)&h3p, h3p_buf);

    gram_kernel<<<dim3(6, BATCH), 256>>>(x, g);

    gemm_mma<GRAMD, N1><<<(N1 + 63) / 64, 128>>>(g,  W1, b1, h1);   // 145 blocks
    gemm_mma<N1,    N2><<<(N2 + 63) / 64, 128>>>(h1, W2, b2, h2);   // 73 blocks

    gemm3_partial<<<dim3(4, N3), 256>>>(h2, W3, h3p);
    final_kernel<<<1, 1024>>>(h3p, b3, W4, b4, out);
}

// round 10
// speedup vs baseline: 2.3257x; 1.2156x over previous
#include <cuda_runtime.h>
#include <math.h>
#include <stdint.h>

// Shapes
#define DIMC 192
#define HW   1024
#define BATCH 32
#define GRAMD 18528   // 192*193/2
#define N1 9264
#define N2 4632
#define N3 64

// Scratch (device globals: no allocation allowed in kernel_launch)
__device__ float g_buf[BATCH * GRAMD];
__device__ float h1_buf[BATCH * N1];
__device__ float h2_buf[BATCH * N2];
__device__ float h3p_buf[4 * BATCH * N3];   // split-K partials for layer 3

// ---------------------------------------------------------------------------
// helpers
// ---------------------------------------------------------------------------
__device__ __forceinline__ void ffma2(unsigned long long& d,
                                      unsigned long long a,
                                      unsigned long long b)
{
    asm("fma.rn.f32x2 %0, %1, %2, %0;" : "+l"(d) : "l"(a), "l"(b));
}

__device__ __forceinline__ float fold_f32x2(unsigned long long v)
{
    float2 f = *reinterpret_cast<float2*>(&v);
    return f.x + f.y;
}

__device__ __forceinline__ uint32_t tf32_of(float f)
{
    uint32_t r;
    asm("cvt.rna.tf32.f32 %0, %1;" : "=r"(r) : "f"(f));
    return r;
}

__device__ __forceinline__ void cp_async16(uint32_t smem_addr, const void* gptr)
{
    asm volatile("cp.async.ca.shared.global [%0], [%1], 16;"
                 :: "r"(smem_addr), "l"(gptr));
}

__device__ __forceinline__ void mma_tf32(float* d, const uint32_t* a,
                                         uint32_t b0, uint32_t b1)
{
    asm volatile(
        "mma.sync.aligned.m16n8k8.row.col.f32.tf32.tf32.f32 "
        "{%0,%1,%2,%3}, {%4,%5,%6,%7}, {%8,%9}, {%0,%1,%2,%3};"
        : "+f"(d[0]), "+f"(d[1]), "+f"(d[2]), "+f"(d[3])
        : "r"(a[0]), "r"(a[1]), "r"(a[2]), "r"(a[3]), "r"(b0), "r"(b1));
}

// ---------------------------------------------------------------------------
// Kernel 1: per-sample Gram upper-triangle features (f32x2 inner loop; proven).
// ---------------------------------------------------------------------------
__global__ void gram_kernel(const float* __restrict__ x, float* __restrict__ g)
{
    __shared__ float As[64][18];
    __shared__ float Bs[64][18];

    const int TI[6] = {0, 0, 0, 1, 1, 2};
    const int TJ[6] = {0, 1, 2, 1, 2, 2};

    int pair = blockIdx.x;
    int b    = blockIdx.y;
    int ti = TI[pair], tj = TJ[pair];

    const float* feat = x + (size_t)b * DIMC * HW;

    int t  = threadIdx.x;
    int ty = t >> 4;
    int tx = t & 15;

    unsigned long long acc[4][4];
    #pragma unroll
    for (int i = 0; i < 4; i++)
        #pragma unroll
        for (int j = 0; j < 4; j++) acc[i][j] = 0ull;

    for (int k0 = 0; k0 < HW; k0 += 16) {
        #pragma unroll
        for (int l = 0; l < 4; l++) {
            int idx = t + l * 256;
            int row = idx >> 4;
            int col = idx & 15;
            As[row][col] = feat[(size_t)(ti * 64 + row) * HW + k0 + col];
            Bs[row][col] = feat[(size_t)(tj * 64 + row) * HW + k0 + col];
        }
        __syncthreads();

        #pragma unroll
        for (int kk = 0; kk < 16; kk += 2) {
            unsigned long long a2[4], b2[4];
            #pragma unroll
            for (int i = 0; i < 4; i++)
                a2[i] = *reinterpret_cast<const unsigned long long*>(&As[ty * 4 + i][kk]);
            #pragma unroll
            for (int j = 0; j < 4; j++)
                b2[j] = *reinterpret_cast<const unsigned long long*>(&Bs[tx * 4 + j][kk]);
            #pragma unroll
            for (int i = 0; i < 4; i++)
                #pragma unroll
                for (int j = 0; j < 4; j++)
                    ffma2(acc[i][j], a2[i], b2[j]);
        }
        __syncthreads();
    }

    #pragma unroll
    for (int i = 0; i < 4; i++) {
        int gi = ti * 64 + ty * 4 + i;
        #pragma unroll
        for (int j = 0; j < 4; j++) {
            int gj = tj * 64 + tx * 4 + j;
            if (gi <= gj) {
                int off = gi * DIMC - (gi * (gi - 1)) / 2 + (gj - gi);
                g[(size_t)b * GRAMD + off] = fold_f32x2(acc[i][j]);
            }
        }
    }
}

// ---------------------------------------------------------------------------
// TF32 tensor-core GEMM + bias + leaky-relu.  out[b][n], b = 0..31.
// Block = 256 threads = 8 warps; triple-buffered cp.async, KC = 48.
// MTILE=64: warp = (n-slice of 16, batch-half of 16 -> 2 btiles)
// MTILE=32: warp = (n-slice of 16, batch-quarter of 8 -> 1 btile)
// Fragment layout verified (R9, rel_err 3.9e-6).
// ---------------------------------------------------------------------------
template <int K, int N, int MTILE>
__global__ __launch_bounds__(256)
void gemm_mma(const float* __restrict__ in, const float* __restrict__ W,
              const float* __restrict__ bias, float* __restrict__ out)
{
    constexpr int KC    = 48;
    constexpr int PITCH = 52;            // floats; 16B-aligned rows, conflict-free
    constexpr int NCH   = K / KC;        // exact for all layers (K % 48 == 0)
    constexpr int NBT   = (MTILE == 64) ? 2 : 1;
    constexpr int WF4   = MTILE * 12;    // float4 loads for W chunk
    constexpr int WRND  = (WF4 + 255) / 256;

    __shared__ float Ws[3][MTILE * PITCH];
    __shared__ float Gs[3][32 * PITCH];

    int tid  = threadIdx.x;
    int lane = tid & 31;
    int warp = tid >> 5;                 // 0..7
    int gid  = lane >> 2;                // 0..7
    int tig  = lane & 3;                 // 0..3
    int n0b  = blockIdx.x * MTILE;

    int nw, bbase;
    if (MTILE == 64) { nw = (warp >> 1) * 16; bbase = (warp & 1) * 16; }
    else             { nw = (warp & 1) * 16;  bbase = (warp >> 1) * 8; }

    float d[NBT][4];
    #pragma unroll
    for (int bt = 0; bt < NBT; bt++)
        #pragma unroll
        for (int r = 0; r < 4; r++) d[bt][r] = 0.0f;

    uint32_t ws_base[3], gs_base[3];
    #pragma unroll
    for (int s = 0; s < 3; s++) {
        ws_base[s] = (uint32_t)__cvta_generic_to_shared(&Ws[s][0]);
        gs_base[s] = (uint32_t)__cvta_generic_to_shared(&Gs[s][0]);
    }

    auto issue = [&](int c) {
        int k0 = c * KC;
        int s  = c % 3;
        #pragma unroll
        for (int r = 0; r < WRND; r++) {
            int f = tid + r * 256;
            if (f < WF4) {
                int row = f / 12;
                int q   = f % 12;
                int grow = n0b + row;
                if (grow >= N) grow = N - 1;        // safe duplicate; stores guarded
                cp_async16(ws_base[s] + (uint32_t)(row * PITCH + q * 4) * 4,
                           W + (size_t)grow * K + k0 + q * 4);
            }
        }
        #pragma unroll
        for (int r = 0; r < 2; r++) {               // 384 float4 over 256 threads
            int f = tid + r * 256;
            if (f < 384) {
                int row = f / 12;
                int q   = f % 12;
                cp_async16(gs_base[s] + (uint32_t)(row * PITCH + q * 4) * 4,
                           in + (size_t)row * K + k0 + q * 4);
            }
        }
        asm volatile("cp.async.commit_group;");
    };

    issue(0);
    if (NCH > 1) issue(1);
    if (NCH > 2) issue(2);

    for (int c = 0; c < NCH; c++) {
        asm volatile("cp.async.wait_group 2;");     // chunk c complete
        __syncthreads();

        int s = c % 3;
        const float* ws = &Ws[s][0];
        const float* gs = &Gs[s][0];

        #pragma unroll
        for (int k8 = 0; k8 < 6; k8++) {
            int kk = k8 * 8;
            uint32_t a[4];
            a[0] = tf32_of(ws[(nw + gid) * PITCH + kk + tig]);
            a[1] = tf32_of(ws[(nw + gid + 8) * PITCH + kk + tig]);
            a[2] = tf32_of(ws[(nw + gid) * PITCH + kk + tig + 4]);
            a[3] = tf32_of(ws[(nw + gid + 8) * PITCH + kk + tig + 4]);
            #pragma unroll
            for (int bt = 0; bt < NBT; bt++) {
                int brow = bbase + bt * 8 + gid;
                uint32_t b0 = tf32_of(gs[brow * PITCH + kk + tig]);
                uint32_t b1 = tf32_of(gs[brow * PITCH + kk + tig + 4]);
                mma_tf32(d[bt], a, b0, b1);
            }
        }
        __syncthreads();                            // all reads of slot s done
        if (c + 3 < NCH) issue(c + 3);              // reuse slot s
    }

    // Epilogue: c0=(gid,2tig) c1=(gid,2tig+1) c2=(gid+8,2tig) c3=(gid+8,2tig+1)
    #pragma unroll
    for (int bt = 0; bt < NBT; bt++) {
        int b   = bbase + bt * 8 + 2 * tig;
        int n_0 = n0b + nw + gid;
        int n_1 = n_0 + 8;
        if (n_0 < N) {
            float bi = bias[n_0];
            float v0 = d[bt][0] + bi; v0 = (v0 > 0.f) ? v0 : 0.01f * v0;
            float v1 = d[bt][1] + bi; v1 = (v1 > 0.f) ? v1 : 0.01f * v1;
            out[(size_t)b * N + n_0]       = v0;
            out[(size_t)(b + 1) * N + n_0] = v1;
        }
        if (n_1 < N) {
            float bi = bias[n_1];
            float v2 = d[bt][2] + bi; v2 = (v2 > 0.f) ? v2 : 0.01f * v2;
            float v3 = d[bt][3] + bi; v3 = (v3 > 0.f) ? v3 : 0.01f * v3;
            out[(size_t)b * N + n_1]       = v2;
            out[(size_t)(b + 1) * N + n_1] = v3;
        }
    }
}

// ---------------------------------------------------------------------------
// Layer 3, split-K partials: grid (4 kslices, 64 n), block 256 (8 warps x 4 b).
// ---------------------------------------------------------------------------
#define N2_F4 (N2 / 4)   // 1158
__global__ __launch_bounds__(256)
void gemm3_partial(const float* __restrict__ in, const float* __restrict__ W,
                   float* __restrict__ part)
{
    int ks   = blockIdx.x;
    int n    = blockIdx.y;
    int lane = threadIdx.x & 31;
    int warp = threadIdx.x >> 5;

    int k4b = ks * 290;
    int k4e = min(N2_F4, k4b + 290);

    const float4* wrow = reinterpret_cast<const float4*>(W + (size_t)n * N2);

    float acc[4] = {0.f, 0.f, 0.f, 0.f};

    for (int i = k4b + lane; i < k4e; i += 32) {
        float4 w = wrow[i];
        #pragma unroll
        for (int j = 0; j < 4; j++) {
            float4 gv = reinterpret_cast<const float4*>(in + (size_t)(warp * 4 + j) * N2)[i];
            acc[j] += w.x * gv.x + w.y * gv.y + w.z * gv.z + w.w * gv.w;
        }
    }

    #pragma unroll
    for (int off = 16; off > 0; off >>= 1)
        #pragma unroll
        for (int j = 0; j < 4; j++)
            acc[j] += __shfl_xor_sync(0xffffffffu, acc[j], off);

    if (lane == 0) {
        #pragma unroll
        for (int j = 0; j < 4; j++)
            part[((size_t)ks * BATCH + warp * 4 + j) * N3 + n] = acc[j];
    }
}

// ---------------------------------------------------------------------------
// Final: reduce split-K partials, + b3, leaky-relu, L2-normalize, dot W4,
// + b4, sigmoid.
// ---------------------------------------------------------------------------
__global__ void final_kernel(const float* __restrict__ part,
                             const float* __restrict__ b3,
                             const float* __restrict__ W4,
                             const float* __restrict__ b4,
                             float* __restrict__ out)
{
    int b    = threadIdx.x >> 5;
    int lane = threadIdx.x & 31;
    int i0 = lane * 2, i1 = lane * 2 + 1;

    float v0 = b3[i0], v1 = b3[i1];
    #pragma unroll
    for (int s = 0; s < 4; s++) {
        v0 += part[((size_t)s * BATCH + b) * N3 + i0];
        v1 += part[((size_t)s * BATCH + b) * N3 + i1];
    }
    v0 = (v0 > 0.f) ? v0 : 0.01f * v0;
    v1 = (v1 > 0.f) ? v1 : 0.01f * v1;

    float ss = v0 * v0 + v1 * v1;
    #pragma unroll
    for (int off = 16; off > 0; off >>= 1)
        ss += __shfl_xor_sync(0xffffffffu, ss, off);

    float denom = fmaxf(sqrtf(ss), 1e-12f);

    float dsum = v0 * W4[i0] + v1 * W4[i1];
    #pragma unroll
    for (int off = 16; off > 0; off >>= 1)
        dsum += __shfl_xor_sync(0xffffffffu, dsum, off);

    if (lane == 0) {
        float logit = dsum / denom + b4[0];
        out[b] = 1.0f / (1.0f + expf(-logit));
    }
}

// ---------------------------------------------------------------------------
// Launch.  Inputs (metadata order): x, W1, b1, W2, b2, W3, b3, W4, b4 (fp32)
// ---------------------------------------------------------------------------
extern "C" void kernel_launch(void* const* d_in, const int* in_sizes, int n_in,
                              void* d_out, int out_size)
{
    const float* x  = (const float*)d_in[0];
    const float* W1 = (const float*)d_in[1];
    const float* b1 = (const float*)d_in[2];
    const float* W2 = (const float*)d_in[3];
    const float* b2 = (const float*)d_in[4];
    const float* W3 = (const float*)d_in[5];
    const float* b3 = (const float*)d_in[6];
    const float* W4 = (const float*)d_in[7];
    const float* b4 = (const float*)d_in[8];
    float* out = (float*)d_out;

    float *g, *h1, *h2, *h3p;
    cudaGetSymbolAddress((void**)&g,   g_buf);
    cudaGetSymbolAddress((void**)&h1,  h1_buf);
    cudaGetSymbolAddress((void**)&h2,  h2_buf);
    cudaGetSymbolAddress((void**)&h3p, h3p_buf);

    gram_kernel<<<dim3(6, BATCH), 256>>>(x, g);

    gemm_mma<GRAMD, N1, 64><<<(N1 + 63) / 64, 256>>>(g,  W1, b1, h1);  // 145 blocks
    gemm_mma<N1,    N2, 32><<<(N2 + 31) / 32, 256>>>(h1, W2, b2, h2);  // 145 blocks

    gemm3_partial<<<dim3(4, N3), 256>>>(h2, W3, h3p);
    final_kernel<<<1, 1024>>>(h3p, b3, W4, b4, out);
}